// round 13
// baseline (speedup 1.0000x reference)
#include <cuda_runtime.h>
#include <cuda_bf16.h>
#include <cuda_fp16.h>
#include <math.h>
#include <stdint.h>

#define BB 4
#define SS 2048
#define HH 1024
#define KK 64
#define NHH 16
#define DH 64
#define LL 2
#define FFD 2730
#define FFH 2752
#define FI2 (2*FFH)
#define EPSV 1e-6f

__device__ float g_x[BB*KK*HH];
__device__ float g_qkv[BB*KK*3*HH];
__device__ int   g_rank[BB*KK];
__device__ float g_q[BB*SS*HH];
__device__ float g_kv[BB*KK*2*HH];
__device__ float g_y[BB*SS*HH];
__device__ float g_yn[BB*SS*HH];

__device__ __half h_tok[BB*SS*HH];
__device__ __half h_h[BB*KK*HH];
__device__ __half h_attn[BB*KK*HH];
__device__ __half h_proc[BB*KK*HH];
__device__ __half h_ff[BB*KK*FFH];
__device__ __half h_dec[BB*SS*HH];
__device__ __half h_yn[BB*SS*HH];
__device__ __half h_u[BB*SS*FFH];

__device__ __half wh_qkv[LL*3*HH*HH];
__device__ __half wh_o[LL*HH*HH];
__device__ __half wh_w13[LL*FI2*HH];
__device__ __half wh_w2[LL*HH*FFH];
__device__ __half wh_din[3*HH*HH];
__device__ __half wh_dout[HH*HH];
__device__ __half wh_dw13[FI2*HH];
__device__ __half wh_dw2[HH*FFH];

__global__ void rank_kernel(const float* __restrict__ cw) {
    int b = blockIdx.x, k = threadIdx.x;
    float wk = cw[b*KK + k];
    int r = 0;
    for (int j = 0; j < KK; j++) {
        float wj = cw[b*KK + j];
        if (wj > wk || (wj == wk && j < k)) r++;
    }
    g_rank[b*KK + k] = r;
}

__global__ void scatter_kernel(const float* __restrict__ src) {
    int row = blockIdx.x;
    int b = row / KK;
    int r = g_rank[row];
    const float* s = src + (size_t)row * HH;
    float* d = g_x + ((size_t)(b*KK + r)) * HH;
    for (int i = threadIdx.x; i < HH; i += blockDim.x) d[i] = s[i];
}

__global__ void gather_kernel() {
    int row = blockIdx.x;
    int b = row / KK;
    int r = g_rank[row];
    const float* s = g_x + ((size_t)(b*KK + r)) * HH;
    __half* d = h_proc + (size_t)row * HH;
    for (int i = threadIdx.x; i < HH; i += blockDim.x) d[i] = __float2half(s[i]);
}

__global__ void halfcopy_kernel(const float* __restrict__ src, __half* __restrict__ dst, int n2) {
    for (int i = blockIdx.x * blockDim.x + threadIdx.x; i < n2; i += gridDim.x * blockDim.x) {
        float2 v = *(const float2*)(src + i*2);
        *(__half2*)(dst + i*2) = __floats2half2_rn(v.x, v.y);
    }
}

__global__ void w13i_kernel(const float* __restrict__ w1, const float* __restrict__ w3,
                            __half* __restrict__ dst) {
    int row = blockIdx.x;
    int c = row >> 1;
    __half* d = dst + (size_t)row * HH;
    if (c < FFD) {
        const float* src = ((row & 1) ? w3 : w1) + (size_t)c * HH;
        for (int i = threadIdx.x*4; i < HH; i += blockDim.x*4) {
            float4 v = *(const float4*)(src + i);
            *(__half2*)(d + i)     = __floats2half2_rn(v.x, v.y);
            *(__half2*)(d + i + 2) = __floats2half2_rn(v.z, v.w);
        }
    } else {
        for (int i = threadIdx.x*4; i < HH; i += blockDim.x*4)
            *(uint2*)(d + i) = make_uint2(0u, 0u);
    }
}

__global__ void w2half_kernel(const float* __restrict__ src, __half* __restrict__ dst) {
    int row = blockIdx.x;
    const float* s = src + (size_t)row * FFD;
    __half* d = dst + (size_t)row * FFH;
    for (int i = threadIdx.x*2; i < FFH; i += blockDim.x*2) {
        float x = 0.f, y = 0.f;
        if (i + 1 < FFD) {
            float2 v = *(const float2*)(s + i);
            x = v.x; y = v.y;
        } else if (i < FFD) {
            x = s[i];
        }
        *(__half2*)(d + i) = __floats2half2_rn(x, y);
    }
}

template<typename TOUT>
__global__ void rms_kernel(const float* __restrict__ in, const float* __restrict__ w,
                           TOUT* __restrict__ out) {
    __shared__ float red[256];
    int row = blockIdx.x;
    const float* x = in + (size_t)row * HH;
    TOUT* o = out + (size_t)row * HH;
    int t = threadIdx.x;
    float v[4];
    float ss = 0.f;
#pragma unroll
    for (int i = 0; i < 4; i++) { v[i] = x[t + i*256]; ss += v[i]*v[i]; }
    red[t] = ss;
    __syncthreads();
    for (int ofs = 128; ofs > 0; ofs >>= 1) {
        if (t < ofs) red[t] += red[t + ofs];
        __syncthreads();
    }
    float inv = rsqrtf(red[0] * (1.0f/HH) + EPSV);
#pragma unroll
    for (int i = 0; i < 4; i++) {
        int c = t + i*256;
        o[c] = (TOUT)(v[i] * inv * w[c]);
    }
}

__global__ void rms2_kernel(const float* __restrict__ in, const float* __restrict__ w1,
                            const float* __restrict__ w2n,
                            float* __restrict__ outy, __half* __restrict__ outh) {
    __shared__ float red[256];
    int row = blockIdx.x;
    const float* x = in + (size_t)row * HH;
    int t = threadIdx.x;
    float v[4];
    float ss = 0.f;
#pragma unroll
    for (int i = 0; i < 4; i++) { v[i] = x[t + i*256]; ss += v[i]*v[i]; }
    red[t] = ss;
    __syncthreads();
    for (int ofs = 128; ofs > 0; ofs >>= 1) {
        if (t < ofs) red[t] += red[t + ofs];
        __syncthreads();
    }
    float inv1 = rsqrtf(red[0] * (1.0f/HH) + EPSV);
    __syncthreads();
    float y[4];
    float ss2 = 0.f;
#pragma unroll
    for (int i = 0; i < 4; i++) {
        int c = t + i*256;
        y[i] = v[i] * inv1 * w1[c];
        ss2 += y[i]*y[i];
    }
    red[t] = ss2;
    __syncthreads();
    for (int ofs = 128; ofs > 0; ofs >>= 1) {
        if (t < ofs) red[t] += red[t + ofs];
        __syncthreads();
    }
    float inv2 = rsqrtf(red[0] * (1.0f/HH) + EPSV);
    float* oy = outy + (size_t)row * HH;
    __half* oh = outh + (size_t)row * HH;
#pragma unroll
    for (int i = 0; i < 4; i++) {
        int c = t + i*256;
        oy[c] = y[i];
        oh[c] = __float2half(y[i] * inv2 * w2n[c]);
    }
}

__device__ __forceinline__ void cp16(uint32_t dst, const void* src, bool pred) {
    int p = pred ? 1 : 0;
    asm volatile(
        "{\n.reg .pred p;\nsetp.ne.b32 p, %2, 0;\n"
        "@p  cp.async.cg.shared.global [%0], [%1], 16;\n"
        "@!p cp.async.cg.shared.global [%0], [%1], 16, 0;\n}"
        :: "r"(dst), "l"(src), "r"(p));
}

__device__ __forceinline__ void ldsm4(uint32_t& r0, uint32_t& r1, uint32_t& r2, uint32_t& r3,
                                      uint32_t addr) {
    asm volatile("ldmatrix.sync.aligned.m8n8.x4.shared.b16 {%0,%1,%2,%3}, [%4];"
                 : "=r"(r0), "=r"(r1), "=r"(r2), "=r"(r3) : "r"(addr));
}

__device__ __forceinline__ void mma_f16(float* d, const uint32_t* a, const uint32_t* b) {
    asm volatile(
        "mma.sync.aligned.m16n8k16.row.col.f32.f16.f16.f32 "
        "{%0,%1,%2,%3}, {%4,%5,%6,%7}, {%8,%9}, {%0,%1,%2,%3};\n"
        : "+f"(d[0]), "+f"(d[1]), "+f"(d[2]), "+f"(d[3])
        : "r"(a[0]), "r"(a[1]), "r"(a[2]), "r"(a[3]), "r"(b[0]), "r"(b[1]));
}

__device__ __forceinline__ float siluf(float x) {
    return x / (1.0f + __expf(-x));
}

#define NTH 512

template<int MB, int NB, int WR, int WC, int GLU>
__global__ __launch_bounds__(NTH) void hgemm(
    const __half* __restrict__ A, int lda,
    const __half* __restrict__ W, int ldw,
    const float* __restrict__ bias, const float* __restrict__ addend, int ldad,
    void* __restrict__ Cv, int ldc, int M, int N, int Kd)
{
    constexpr int MI  = MB / WR / 16;
    constexpr int NI  = NB / WC / 8;
    constexpr int ACH = MB * 8 / NTH;
    constexpr int BCH = NB * 8 / NTH;
    constexpr int ASZB = MB * 128;
    constexpr int BSZB = NB * 128;
    constexpr int STGB = ASZB + BSZB;

    extern __shared__ char smc[];
    const uint32_t sbase = (uint32_t)__cvta_generic_to_shared(smc);
    const int tid  = threadIdx.x;
    const int lane = tid & 31;
    const int wid  = tid >> 5;
    const int wr   = wid / WC, wc = wid % WC;
    const int mb0  = wr * MI;
    const int nb0  = wc * NI;

    // L2-locality swizzle: groups of 8 M-tiles walk N inside the group
    const int nT = gridDim.x;
    const int mT = gridDim.y;
    int lin = blockIdx.y * nT + blockIdx.x;
    const int G = 8;
    int perGroup = G * nT;
    int grp = lin / perGroup;
    int rem = lin - grp * perGroup;
    int gsz = mT - grp * G; if (gsz > G) gsz = G;
    int gm = grp * G + rem % gsz;
    int gn = rem / gsz;
    const int bm = gm * MB, bn = gn * NB;

    float acc[MI][NI][4];
#pragma unroll
    for (int i = 0; i < MI; i++)
#pragma unroll
        for (int n = 0; n < NI; n++)
#pragma unroll
            for (int q = 0; q < 4; q++) acc[i][n][q] = 0.f;

    const int T = Kd >> 6;

    auto fill = [&](int t) {
        int st = t - (t/3)*3;
        uint32_t ab = sbase + st*STGB;
        uint32_t bb = ab + ASZB;
        int k0 = t * 64;
#pragma unroll
        for (int ch = 0; ch < ACH; ch++) {
            int idx = tid + ch*NTH;
            int row = idx >> 3, c = idx & 7;
            uint32_t dst = ab + row*128 + ((c ^ (row & 7)) << 4);
            cp16(dst, A + (size_t)(bm + row)*lda + k0 + c*8, true);
        }
#pragma unroll
        for (int ch = 0; ch < BCH; ch++) {
            int idx = tid + ch*NTH;
            int row = idx >> 3, c = idx & 7;
            int gnn = bn + row;
            bool p = gnn < N;
            uint32_t dst = bb + row*128 + ((c ^ (row & 7)) << 4);
            cp16(dst, W + (size_t)(p ? gnn : 0)*ldw + k0 + c*8, p);
        }
        asm volatile("cp.async.commit_group;" ::: "memory");
    };

    const int mi = lane >> 3;
    const int aRowLoc = (mi & 1)*8 + (lane & 7);
    const int aCb = mi >> 1;
    const int bRowLoc = lane & 7;
    const int bBlk = mi >> 1;
    const int bCb = mi & 1;
    uint32_t aRowOff[MI], aS[MI];
#pragma unroll
    for (int i = 0; i < MI; i++) {
        int row = (mb0 + i)*16 + aRowLoc;
        aRowOff[i] = row*128;
        aS[i] = (row & 7) << 4;
    }
    uint32_t bRowOff[NI/2], bS[NI/2];
#pragma unroll
    for (int j = 0; j < NI/2; j++) {
        int nr = (nb0 + j*2 + bBlk)*8 + bRowLoc;
        bRowOff[j] = nr*128;
        bS[j] = (nr & 7) << 4;
    }

    fill(0);
    fill(1);

    for (int t = 0; t < T; t++) {
        if (t == T - 1)
            asm volatile("cp.async.wait_group 0;" ::: "memory");
        else
            asm volatile("cp.async.wait_group 1;" ::: "memory");
        __syncthreads();
        int st = t - (t/3)*3;
        uint32_t ab = sbase + st*STGB;
        uint32_t bb = ab + ASZB;
#pragma unroll
        for (int kb = 0; kb < 4; kb++) {
            uint32_t af[MI][4];
#pragma unroll
            for (int i = 0; i < MI; i++)
                ldsm4(af[i][0], af[i][1], af[i][2], af[i][3],
                      ab + aRowOff[i] + ((((kb*2 + aCb) << 4)) ^ aS[i]));
            uint32_t bf[NI][2];
#pragma unroll
            for (int j = 0; j < NI/2; j++)
                ldsm4(bf[j*2][0], bf[j*2][1], bf[j*2+1][0], bf[j*2+1][1],
                      bb + bRowOff[j] + ((((kb*2 + bCb) << 4)) ^ bS[j]));
#pragma unroll
            for (int i = 0; i < MI; i++)
#pragma unroll
                for (int n = 0; n < NI; n++)
                    mma_f16(acc[i][n], af[i], bf[n]);
        }
        if (t + 2 < T) fill(t + 2);
    }

    const int g = lane >> 2, tg = lane & 3;
    if (GLU) {
        __half* Ch = (__half*)Cv;
#pragma unroll
        for (int i = 0; i < MI; i++) {
            int r0 = bm + (mb0 + i)*16 + g;
            int r1 = r0 + 8;
#pragma unroll
            for (int n = 0; n < NI; n++) {
                int gnn = bn + (nb0 + n)*8 + tg*2;
                if (gnn < N) {
                    int col = gnn >> 1;
                    Ch[(size_t)r0*ldc + col] = __float2half(siluf(acc[i][n][0]) * acc[i][n][1]);
                    Ch[(size_t)r1*ldc + col] = __float2half(siluf(acc[i][n][2]) * acc[i][n][3]);
                }
            }
        }
    } else {
        float* C = (float*)Cv;
#pragma unroll
        for (int i = 0; i < MI; i++) {
            int r0 = bm + (mb0 + i)*16 + g;
            int r1 = r0 + 8;
#pragma unroll
            for (int n = 0; n < NI; n++) {
                int gnn = bn + (nb0 + n)*8 + tg*2;
                if (gnn < N) {
                    float b0 = 0.f, b1 = 0.f;
                    if (bias) { b0 = bias[gnn]; b1 = bias[gnn+1]; }
                    float v0 = acc[i][n][0] + b0, v1 = acc[i][n][1] + b1;
                    float v2 = acc[i][n][2] + b0, v3 = acc[i][n][3] + b1;
                    if (addend) {
                        float2 a0 = *(const float2*)(addend + (size_t)r0*ldad + gnn);
                        float2 a1 = *(const float2*)(addend + (size_t)r1*ldad + gnn);
                        v0 += a0.x; v1 += a0.y; v2 += a1.x; v3 += a1.y;
                    }
                    *(float2*)(C + (size_t)r0*ldc + gnn) = make_float2(v0, v1);
                    *(float2*)(C + (size_t)r1*ldc + gnn) = make_float2(v2, v3);
                }
            }
        }
    }
}

__global__ void casc_attn_kernel() {
    __shared__ float ks[KK][DH+1];
    __shared__ float vs[KK][DH+1];
    int bh = blockIdx.x;
    int b = bh / NHH, nh = bh % NHH;
    int t = threadIdx.x;
    const float* base = g_qkv + ((size_t)(b*KK + t)) * (3*HH);
#pragma unroll
    for (int dd = 0; dd < DH; dd++) {
        ks[t][dd] = base[HH   + nh*DH + dd];
        vs[t][dd] = base[2*HH + nh*DH + dd];
    }
    __syncthreads();
    float q[DH];
#pragma unroll
    for (int dd = 0; dd < DH; dd++) q[dd] = base[nh*DH + dd];

    const float scale = 0.125f;
    float sc[KK];
    float mx = -1e30f;
    for (int j = 0; j <= t; j++) {
        float s = 0.f;
#pragma unroll
        for (int dd = 0; dd < DH; dd++) s += q[dd] * ks[j][dd];
        s *= scale;
        sc[j] = s;
        mx = fmaxf(mx, s);
    }
    float sum = 0.f;
    for (int j = 0; j <= t; j++) {
        float e = expf(sc[j] - mx);
        sc[j] = e;
        sum += e;
    }
    float inv = 1.0f / sum;
    __half* o = h_attn + ((size_t)(b*KK + t)) * HH + nh*DH;
#pragma unroll 4
    for (int dd = 0; dd < DH; dd++) {
        float acc = 0.f;
        for (int j = 0; j <= t; j++) acc += sc[j] * vs[j][dd];
        o[dd] = __float2half(acc * inv);
    }
}

__global__ void dec_attn_kernel() {
    __shared__ float ks[KK][DH+1];
    __shared__ float vs[KK][DH+1];
    __shared__ float qs[8][DH];
    __shared__ float probs[8][KK];
    int nh = blockIdx.x, b = blockIdx.y, z = blockIdx.z;
    int tid = threadIdx.x;
    for (int i = tid; i < KK*DH; i += 256) {
        int c = i / DH, dd = i % DH;
        const float* kvrow = g_kv + ((size_t)(b*KK + c)) * (2*HH);
        ks[c][dd] = kvrow[nh*DH + dd];
        vs[c][dd] = kvrow[HH + nh*DH + dd];
    }
    __syncthreads();
    int w = tid >> 5, lane = tid & 31;
    const float scale = 0.125f;
    const int s0b = z * (SS/8), s1b = s0b + (SS/8);
    for (int s = s0b + w; s < s1b; s += 8) {
        int nallow = min(KK, s/32 + 2);
        const float* qrow = g_q + ((size_t)b*SS + s) * HH + nh*DH;
        qs[w][lane]      = qrow[lane];
        qs[w][lane + 32] = qrow[lane + 32];
        __syncwarp();
        float s0 = -INFINITY, s1 = -INFINITY;
        if (lane < nallow) {
            float acc = 0.f;
#pragma unroll
            for (int dd = 0; dd < DH; dd++) acc += qs[w][dd] * ks[lane][dd];
            s0 = acc * scale;
        }
        if (lane + 32 < nallow) {
            float acc = 0.f;
#pragma unroll
            for (int dd = 0; dd < DH; dd++) acc += qs[w][dd] * ks[lane + 32][dd];
            s1 = acc * scale;
        }
        float mx = fmaxf(s0, s1);
#pragma unroll
        for (int ofs = 16; ofs > 0; ofs >>= 1)
            mx = fmaxf(mx, __shfl_xor_sync(0xffffffffu, mx, ofs));
        float e0 = expf(s0 - mx);
        float e1 = expf(s1 - mx);
        float sum = e0 + e1;
#pragma unroll
        for (int ofs = 16; ofs > 0; ofs >>= 1)
            sum += __shfl_xor_sync(0xffffffffu, sum, ofs);
        float inv = 1.0f / sum;
        probs[w][lane]      = e0 * inv;
        probs[w][lane + 32] = e1 * inv;
        __syncwarp();
        __half* orow = h_dec + ((size_t)b*SS + s) * HH + nh*DH;
#pragma unroll
        for (int half2i = 0; half2i < 2; half2i++) {
            int dd = lane + half2i*32;
            float acc = 0.f;
            for (int j = 0; j < nallow; j++) acc += probs[w][j] * vs[j][dd];
            orow[dd] = __float2half(acc);
        }
        __syncwarp();
    }
}

template<typename T>
static T* symaddr(const void* sym) {
    void* p = nullptr;
    cudaGetSymbolAddress(&p, sym);
    return (T*)p;
}

#define SMEM_D (3*(128 + 256)*128)
#define SMEM_C (3*(64  + 128)*128)

extern "C" void kernel_launch(void* const* d_in, const int* in_sizes, int n_in,
                              void* d_out, int out_size) {
    const float* token       = (const float*)d_in[0];
    const float* chunk_repr  = (const float*)d_in[1];
    const float* cw          = (const float*)d_in[2];
    const float* casc_norm1  = (const float*)d_in[3];
    const float* casc_qkv    = (const float*)d_in[4];
    const float* casc_o      = (const float*)d_in[5];
    const float* casc_norm2  = (const float*)d_in[6];
    const float* casc_w1     = (const float*)d_in[7];
    const float* casc_w2     = (const float*)d_in[8];
    const float* casc_w3     = (const float*)d_in[9];
    const float* dec_in_w    = (const float*)d_in[10];
    const float* dec_in_b    = (const float*)d_in[11];
    const float* dec_out_w   = (const float*)d_in[12];
    const float* dec_out_b   = (const float*)d_in[13];
    const float* dec_norm_w  = (const float*)d_in[14];
    const float* dec_ffn_nw  = (const float*)d_in[15];
    const float* dec_w1      = (const float*)d_in[16];
    const float* dec_w2      = (const float*)d_in[17];
    const float* dec_w3      = (const float*)d_in[18];
    float* out = (float*)d_out;

    float* px    = symaddr<float>(g_x);
    float* pqkv  = symaddr<float>(g_qkv);
    float* pq    = symaddr<float>(g_q);
    float* pkv   = symaddr<float>(g_kv);
    float* py    = symaddr<float>(g_y);
    float* pyn   = symaddr<float>(g_yn);

    __half* ph_tok  = symaddr<__half>(h_tok);
    __half* ph_h    = symaddr<__half>(h_h);
    __half* ph_attn = symaddr<__half>(h_attn);
    __half* ph_proc = symaddr<__half>(h_proc);
    __half* ph_ff   = symaddr<__half>(h_ff);
    __half* ph_dec  = symaddr<__half>(h_dec);
    __half* ph_yn   = symaddr<__half>(h_yn);
    __half* ph_u    = symaddr<__half>(h_u);

    __half* pw_qkv  = symaddr<__half>(wh_qkv);
    __half* pw_o    = symaddr<__half>(wh_o);
    __half* pw_w13  = symaddr<__half>(wh_w13);
    __half* pw_w2   = symaddr<__half>(wh_w2);
    __half* pw_din  = symaddr<__half>(wh_din);
    __half* pw_dout = symaddr<__half>(wh_dout);
    __half* pw_dw13 = symaddr<__half>(wh_dw13);
    __half* pw_dw2  = symaddr<__half>(wh_dw2);

    cudaFuncSetAttribute((const void*)hgemm<128,256,2,8,0>,
                         cudaFuncAttributeMaxDynamicSharedMemorySize, SMEM_D);
    cudaFuncSetAttribute((const void*)hgemm<128,256,2,8,1>,
                         cudaFuncAttributeMaxDynamicSharedMemorySize, SMEM_D);
    cudaFuncSetAttribute((const void*)hgemm<64,128,2,8,0>,
                         cudaFuncAttributeMaxDynamicSharedMemorySize, SMEM_C);
    cudaFuncSetAttribute((const void*)hgemm<64,128,2,8,1>,
                         cudaFuncAttributeMaxDynamicSharedMemorySize, SMEM_C);

    auto gemmD = [&](cudaStream_t st, const __half* A, int lda, const __half* W, int ldw,
                     const float* bias, const float* addend, int ldad,
                     void* C, int ldc, int M, int N, int Kd, bool glu) {
        dim3 grid((N + 255)/256, M/128);
        if (glu)
            hgemm<128,256,2,8,1><<<grid, NTH, SMEM_D, st>>>(A, lda, W, ldw, bias, addend, ldad,
                                                            C, ldc, M, N, Kd);
        else
            hgemm<128,256,2,8,0><<<grid, NTH, SMEM_D, st>>>(A, lda, W, ldw, bias, addend, ldad,
                                                            C, ldc, M, N, Kd);
    };
    auto gemmC = [&](cudaStream_t st, const __half* A, int lda, const __half* W, int ldw,
                     const float* bias, const float* addend, int ldad,
                     void* C, int ldc, int M, int N, int Kd, bool glu) {
        dim3 grid((N + 127)/128, M/64);
        if (glu)
            hgemm<64,128,2,8,1><<<grid, NTH, SMEM_C, st>>>(A, lda, W, ldw, bias, addend, ldad,
                                                           C, ldc, M, N, Kd);
        else
            hgemm<64,128,2,8,0><<<grid, NTH, SMEM_C, st>>>(A, lda, W, ldw, bias, addend, ldad,
                                                           C, ldc, M, N, Kd);
    };

    cudaStream_t main0 = 0;
    cudaStream_t side;
    cudaStreamCreateWithFlags(&side, cudaStreamNonBlocking);
    cudaEvent_t evFork, ev1, ev2, ev3;
    cudaEventCreateWithFlags(&evFork, cudaEventDisableTiming);
    cudaEventCreateWithFlags(&ev1, cudaEventDisableTiming);
    cudaEventCreateWithFlags(&ev2, cudaEventDisableTiming);
    cudaEventCreateWithFlags(&ev3, cudaEventDisableTiming);

    // ---- fork ----
    cudaEventRecord(evFork, main0);
    cudaStreamWaitEvent(side, evFork, 0);
    // side: din + token + q projection first (critical for dec_attn)
    halfcopy_kernel<<<2048, 256, 0, side>>>(dec_in_w,  pw_din,  3*HH*HH/2);
    halfcopy_kernel<<<4096, 256, 0, side>>>(token, ph_tok, BB*SS*HH/2);
    gemmD(side, ph_tok, HH, pw_din, HH,
          dec_in_b, nullptr, 0, pq, HH, BB*SS, HH, HH, false);
    cudaEventRecord(ev1, side);                 // din + q ready
    // side: cascade layer-1 ff weight prep (needed mid-cascade)
    w13i_kernel<<<FI2, 256, 0, side>>>(casc_w1 + (size_t)FFD*HH,
                                       casc_w3 + (size_t)FFD*HH,
                                       pw_w13 + (size_t)FI2*HH);
    w2half_kernel<<<HH, 256, 0, side>>>(casc_w2 + (size_t)HH*FFD,
                                        pw_w2 + (size_t)HH*FFH);
    cudaEventRecord(ev3, side);                 // layer-1 ff weights ready
    // side: remaining decoder weight prep
    halfcopy_kernel<<<2048, 256, 0, side>>>(dec_out_w, pw_dout, HH*HH/2);
    w13i_kernel<<<FI2, 256, 0, side>>>(dec_w1, dec_w3, pw_dw13);
    w2half_kernel<<<HH, 256, 0, side>>>(dec_w2, pw_dw2);
    cudaEventRecord(ev2, side);                 // all decoder weights ready

    // ---- main: cascade (layer-0 prep only) ----
    halfcopy_kernel<<<2048, 256>>>(casc_qkv, pw_qkv, LL*3*HH*HH/2);
    halfcopy_kernel<<<2048, 256>>>(casc_o,   pw_o,   LL*HH*HH/2);
    w13i_kernel<<<FI2, 256>>>(casc_w1, casc_w3, pw_w13);
    w2half_kernel<<<HH, 256>>>(casc_w2, pw_w2);
    rank_kernel<<<BB, KK>>>(cw);
    scatter_kernel<<<BB*KK, 256>>>(chunk_repr);

    const int MC = BB*KK;
    for (int l = 0; l < LL; l++) {
        rms_kernel<__half><<<MC, 256>>>(px, casc_norm1 + l*HH, ph_h);
        gemmC(main0, ph_h, HH, pw_qkv + (size_t)l*3*HH*HH, HH,
              nullptr, nullptr, 0, pqkv, 3*HH, MC, 3*HH, HH, false);
        casc_attn_kernel<<<BB*NHH, KK>>>();
        gemmC(main0, ph_attn, HH, pw_o + (size_t)l*HH*HH, HH,
              nullptr, px, HH, px, HH, MC, HH, HH, false);
        rms_kernel<__half><<<MC, 256>>>(px, casc_norm2 + l*HH, ph_h);
        if (l == 1) cudaStreamWaitEvent(main0, ev3, 0);   // layer-1 ff weights
        gemmC(main0, ph_h, HH, pw_w13 + (size_t)l*FI2*HH, HH,
              nullptr, nullptr, 0, ph_ff, FFH, MC, FI2, HH, true);
        gemmC(main0, ph_ff, FFH, pw_w2 + (size_t)l*HH*FFH, FFH,
              nullptr, px, HH, px, HH, MC, HH, FFH, false);
    }
    gather_kernel<<<BB*KK, 256>>>();

    // ---- kv gemm needs din + q (ev1) ----
    cudaStreamWaitEvent(main0, ev1, 0);
    gemmC(main0, ph_proc, HH, pw_din + (size_t)HH*HH, HH,
          dec_in_b + HH, nullptr, 0, pkv, 2*HH, MC, 2*HH, HH, false);
    dec_attn_kernel<<<dim3(NHH, BB, 8), 256>>>();

    // ---- rest needs all decoder weights (ev2) ----
    cudaStreamWaitEvent(main0, ev2, 0);
    const int MT = BB*SS;
    gemmD(main0, ph_dec, HH, pw_dout, HH,
          dec_out_b, token, HH, pyn, HH, MT, HH, HH, false);
    rms2_kernel<<<MT, 256>>>(pyn, dec_norm_w, dec_ffn_nw, py, ph_yn);
    gemmD(main0, ph_yn, HH, pw_dw13, HH,
          nullptr, nullptr, 0, ph_u, FFH, MT, FI2, HH, true);
    gemmD(main0, ph_u, FFH, pw_dw2, FFH,
          nullptr, py, HH, out, HH, MT, HH, FFH, false);
}

// round 14
// speedup vs baseline: 1.1494x; 1.1494x over previous
#include <cuda_runtime.h>
#include <cuda_bf16.h>
#include <cuda_fp16.h>
#include <math.h>
#include <stdint.h>

#define BB 4
#define SS 2048
#define HH 1024
#define KK 64
#define NHH 16
#define DH 64
#define LL 2
#define FFD 2730
#define FFH 2752
#define FI2 (2*FFH)
#define EPSV 1e-6f

__device__ float g_x[BB*KK*HH];
__device__ float g_qkv[BB*KK*3*HH];
__device__ int   g_rank[BB*KK];
__device__ float g_q[BB*SS*HH];
__device__ float g_kv[BB*KK*2*HH];
__device__ float g_y[BB*SS*HH];
__device__ float g_yn[BB*SS*HH];

__device__ __half h_tok[BB*SS*HH];
__device__ __half h_h[BB*KK*HH];
__device__ __half h_attn[BB*KK*HH];
__device__ __half h_proc[BB*KK*HH];
__device__ __half h_ff[BB*KK*FFH];
__device__ __half h_dec[BB*SS*HH];
__device__ __half h_yn[BB*SS*HH];
__device__ __half h_u[BB*SS*FFH];

__device__ __half wh_qkv[LL*3*HH*HH];
__device__ __half wh_o[LL*HH*HH];
__device__ __half wh_w13[LL*FI2*HH];
__device__ __half wh_w2[LL*HH*FFH];
__device__ __half wh_din[3*HH*HH];
__device__ __half wh_dout[HH*HH];
__device__ __half wh_dw13[FI2*HH];
__device__ __half wh_dw2[HH*FFH];

__global__ void rank_kernel(const float* __restrict__ cw) {
    int b = blockIdx.x, k = threadIdx.x;
    float wk = cw[b*KK + k];
    int r = 0;
    for (int j = 0; j < KK; j++) {
        float wj = cw[b*KK + j];
        if (wj > wk || (wj == wk && j < k)) r++;
    }
    g_rank[b*KK + k] = r;
}

__global__ void scatter_kernel(const float* __restrict__ src) {
    int row = blockIdx.x;
    int b = row / KK;
    int r = g_rank[row];
    const float* s = src + (size_t)row * HH;
    float* d = g_x + ((size_t)(b*KK + r)) * HH;
    for (int i = threadIdx.x; i < HH; i += blockDim.x) d[i] = s[i];
}

__global__ void gather_kernel() {
    int row = blockIdx.x;
    int b = row / KK;
    int r = g_rank[row];
    const float* s = g_x + ((size_t)(b*KK + r)) * HH;
    __half* d = h_proc + (size_t)row * HH;
    for (int i = threadIdx.x; i < HH; i += blockDim.x) d[i] = __float2half(s[i]);
}

__global__ void halfcopy_kernel(const float* __restrict__ src, __half* __restrict__ dst, int n2) {
    for (int i = blockIdx.x * blockDim.x + threadIdx.x; i < n2; i += gridDim.x * blockDim.x) {
        float2 v = *(const float2*)(src + i*2);
        *(__half2*)(dst + i*2) = __floats2half2_rn(v.x, v.y);
    }
}

__global__ void w13i_kernel(const float* __restrict__ w1, const float* __restrict__ w3,
                            __half* __restrict__ dst) {
    int row = blockIdx.x;
    int c = row >> 1;
    __half* d = dst + (size_t)row * HH;
    if (c < FFD) {
        const float* src = ((row & 1) ? w3 : w1) + (size_t)c * HH;
        for (int i = threadIdx.x*4; i < HH; i += blockDim.x*4) {
            float4 v = *(const float4*)(src + i);
            *(__half2*)(d + i)     = __floats2half2_rn(v.x, v.y);
            *(__half2*)(d + i + 2) = __floats2half2_rn(v.z, v.w);
        }
    } else {
        for (int i = threadIdx.x*4; i < HH; i += blockDim.x*4)
            *(uint2*)(d + i) = make_uint2(0u, 0u);
    }
}

__global__ void w2half_kernel(const float* __restrict__ src, __half* __restrict__ dst) {
    int row = blockIdx.x;
    const float* s = src + (size_t)row * FFD;
    __half* d = dst + (size_t)row * FFH;
    for (int i = threadIdx.x*2; i < FFH; i += blockDim.x*2) {
        float x = 0.f, y = 0.f;
        if (i + 1 < FFD) {
            float2 v = *(const float2*)(s + i);
            x = v.x; y = v.y;
        } else if (i < FFD) {
            x = s[i];
        }
        *(__half2*)(d + i) = __floats2half2_rn(x, y);
    }
}

template<typename TOUT>
__global__ void rms_kernel(const float* __restrict__ in, const float* __restrict__ w,
                           TOUT* __restrict__ out) {
    __shared__ float red[256];
    int row = blockIdx.x;
    const float* x = in + (size_t)row * HH;
    TOUT* o = out + (size_t)row * HH;
    int t = threadIdx.x;
    float v[4];
    float ss = 0.f;
#pragma unroll
    for (int i = 0; i < 4; i++) { v[i] = x[t + i*256]; ss += v[i]*v[i]; }
    red[t] = ss;
    __syncthreads();
    for (int ofs = 128; ofs > 0; ofs >>= 1) {
        if (t < ofs) red[t] += red[t + ofs];
        __syncthreads();
    }
    float inv = rsqrtf(red[0] * (1.0f/HH) + EPSV);
#pragma unroll
    for (int i = 0; i < 4; i++) {
        int c = t + i*256;
        o[c] = (TOUT)(v[i] * inv * w[c]);
    }
}

__global__ void rms2_kernel(const float* __restrict__ in, const float* __restrict__ w1,
                            const float* __restrict__ w2n,
                            float* __restrict__ outy, __half* __restrict__ outh) {
    __shared__ float red[256];
    int row = blockIdx.x;
    const float* x = in + (size_t)row * HH;
    int t = threadIdx.x;
    float v[4];
    float ss = 0.f;
#pragma unroll
    for (int i = 0; i < 4; i++) { v[i] = x[t + i*256]; ss += v[i]*v[i]; }
    red[t] = ss;
    __syncthreads();
    for (int ofs = 128; ofs > 0; ofs >>= 1) {
        if (t < ofs) red[t] += red[t + ofs];
        __syncthreads();
    }
    float inv1 = rsqrtf(red[0] * (1.0f/HH) + EPSV);
    __syncthreads();
    float y[4];
    float ss2 = 0.f;
#pragma unroll
    for (int i = 0; i < 4; i++) {
        int c = t + i*256;
        y[i] = v[i] * inv1 * w1[c];
        ss2 += y[i]*y[i];
    }
    red[t] = ss2;
    __syncthreads();
    for (int ofs = 128; ofs > 0; ofs >>= 1) {
        if (t < ofs) red[t] += red[t + ofs];
        __syncthreads();
    }
    float inv2 = rsqrtf(red[0] * (1.0f/HH) + EPSV);
    float* oy = outy + (size_t)row * HH;
    __half* oh = outh + (size_t)row * HH;
#pragma unroll
    for (int i = 0; i < 4; i++) {
        int c = t + i*256;
        oy[c] = y[i];
        oh[c] = __float2half(y[i] * inv2 * w2n[c]);
    }
}

__device__ __forceinline__ void cp16(uint32_t dst, const void* src, bool pred) {
    int p = pred ? 1 : 0;
    asm volatile(
        "{\n.reg .pred p;\nsetp.ne.b32 p, %2, 0;\n"
        "@p  cp.async.cg.shared.global [%0], [%1], 16;\n"
        "@!p cp.async.cg.shared.global [%0], [%1], 16, 0;\n}"
        :: "r"(dst), "l"(src), "r"(p));
}

__device__ __forceinline__ void ldsm4(uint32_t& r0, uint32_t& r1, uint32_t& r2, uint32_t& r3,
                                      uint32_t addr) {
    asm volatile("ldmatrix.sync.aligned.m8n8.x4.shared.b16 {%0,%1,%2,%3}, [%4];"
                 : "=r"(r0), "=r"(r1), "=r"(r2), "=r"(r3) : "r"(addr));
}

__device__ __forceinline__ void mma_f16(float* d, const uint32_t* a, const uint32_t* b) {
    asm volatile(
        "mma.sync.aligned.m16n8k16.row.col.f32.f16.f16.f32 "
        "{%0,%1,%2,%3}, {%4,%5,%6,%7}, {%8,%9}, {%0,%1,%2,%3};\n"
        : "+f"(d[0]), "+f"(d[1]), "+f"(d[2]), "+f"(d[3])
        : "r"(a[0]), "r"(a[1]), "r"(a[2]), "r"(a[3]), "r"(b[0]), "r"(b[1]));
}

__device__ __forceinline__ float siluf(float x) {
    return x / (1.0f + __expf(-x));
}

#define NTH 512

template<int MB, int NB, int WR, int WC, int GLU>
__global__ __launch_bounds__(NTH) void hgemm(
    const __half* __restrict__ A, int lda,
    const __half* __restrict__ W, int ldw,
    const float* __restrict__ bias, const float* __restrict__ addend, int ldad,
    void* __restrict__ Cv, int ldc, int M, int N, int Kd)
{
    constexpr int MI  = MB / WR / 16;
    constexpr int NI  = NB / WC / 8;
    constexpr int ACH = MB * 8 / NTH;
    constexpr int BCH = NB * 8 / NTH;
    constexpr int ASZB = MB * 128;
    constexpr int BSZB = NB * 128;
    constexpr int STGB = ASZB + BSZB;

    extern __shared__ char smc[];
    const uint32_t sbase = (uint32_t)__cvta_generic_to_shared(smc);
    const int tid  = threadIdx.x;
    const int lane = tid & 31;
    const int wid  = tid >> 5;
    const int wr   = wid / WC, wc = wid % WC;
    const int mb0  = wr * MI;
    const int nb0  = wc * NI;
    const int bm = blockIdx.y * MB, bn = blockIdx.x * NB;

    float acc[MI][NI][4];
#pragma unroll
    for (int i = 0; i < MI; i++)
#pragma unroll
        for (int n = 0; n < NI; n++)
#pragma unroll
            for (int q = 0; q < 4; q++) acc[i][n][q] = 0.f;

    const int T = Kd >> 6;

    auto fill = [&](int t) {
        int st = t - (t/3)*3;
        uint32_t ab = sbase + st*STGB;
        uint32_t bb = ab + ASZB;
        int k0 = t * 64;
#pragma unroll
        for (int ch = 0; ch < ACH; ch++) {
            int idx = tid + ch*NTH;
            int row = idx >> 3, c = idx & 7;
            uint32_t dst = ab + row*128 + ((c ^ (row & 7)) << 4);
            cp16(dst, A + (size_t)(bm + row)*lda + k0 + c*8, true);
        }
#pragma unroll
        for (int ch = 0; ch < BCH; ch++) {
            int idx = tid + ch*NTH;
            int row = idx >> 3, c = idx & 7;
            int gn = bn + row;
            bool p = gn < N;
            uint32_t dst = bb + row*128 + ((c ^ (row & 7)) << 4);
            cp16(dst, W + (size_t)(p ? gn : 0)*ldw + k0 + c*8, p);
        }
        asm volatile("cp.async.commit_group;" ::: "memory");
    };

    const int mi = lane >> 3;
    const int aRowLoc = (mi & 1)*8 + (lane & 7);
    const int aCb = mi >> 1;
    const int bRowLoc = lane & 7;
    const int bBlk = mi >> 1;
    const int bCb = mi & 1;
    uint32_t aRowOff[MI], aS[MI];
#pragma unroll
    for (int i = 0; i < MI; i++) {
        int row = (mb0 + i)*16 + aRowLoc;
        aRowOff[i] = row*128;
        aS[i] = (row & 7) << 4;
    }
    uint32_t bRowOff[NI/2], bS[NI/2];
#pragma unroll
    for (int j = 0; j < NI/2; j++) {
        int nr = (nb0 + j*2 + bBlk)*8 + bRowLoc;
        bRowOff[j] = nr*128;
        bS[j] = (nr & 7) << 4;
    }

    fill(0);
    fill(1);

    for (int t = 0; t < T; t++) {
        if (t == T - 1)
            asm volatile("cp.async.wait_group 0;" ::: "memory");
        else
            asm volatile("cp.async.wait_group 1;" ::: "memory");
        __syncthreads();
        int st = t - (t/3)*3;
        uint32_t ab = sbase + st*STGB;
        uint32_t bb = ab + ASZB;
#pragma unroll
        for (int kb = 0; kb < 4; kb++) {
            uint32_t af[MI][4];
#pragma unroll
            for (int i = 0; i < MI; i++)
                ldsm4(af[i][0], af[i][1], af[i][2], af[i][3],
                      ab + aRowOff[i] + ((((kb*2 + aCb) << 4)) ^ aS[i]));
            uint32_t bf[NI][2];
#pragma unroll
            for (int j = 0; j < NI/2; j++)
                ldsm4(bf[j*2][0], bf[j*2][1], bf[j*2+1][0], bf[j*2+1][1],
                      bb + bRowOff[j] + ((((kb*2 + bCb) << 4)) ^ bS[j]));
#pragma unroll
            for (int i = 0; i < MI; i++)
#pragma unroll
                for (int n = 0; n < NI; n++)
                    mma_f16(acc[i][n], af[i], bf[n]);
        }
        if (t + 2 < T) fill(t + 2);
    }

    const int g = lane >> 2, tg = lane & 3;
    if (GLU) {
        __half* Ch = (__half*)Cv;
#pragma unroll
        for (int i = 0; i < MI; i++) {
            int r0 = bm + (mb0 + i)*16 + g;
            int r1 = r0 + 8;
#pragma unroll
            for (int n = 0; n < NI; n++) {
                int gn = bn + (nb0 + n)*8 + tg*2;
                if (gn < N) {
                    int col = gn >> 1;
                    Ch[(size_t)r0*ldc + col] = __float2half(siluf(acc[i][n][0]) * acc[i][n][1]);
                    Ch[(size_t)r1*ldc + col] = __float2half(siluf(acc[i][n][2]) * acc[i][n][3]);
                }
            }
        }
    } else {
        float* C = (float*)Cv;
#pragma unroll
        for (int i = 0; i < MI; i++) {
            int r0 = bm + (mb0 + i)*16 + g;
            int r1 = r0 + 8;
#pragma unroll
            for (int n = 0; n < NI; n++) {
                int gn = bn + (nb0 + n)*8 + tg*2;
                if (gn < N) {
                    float b0 = 0.f, b1 = 0.f;
                    if (bias) { b0 = bias[gn]; b1 = bias[gn+1]; }
                    float v0 = acc[i][n][0] + b0, v1 = acc[i][n][1] + b1;
                    float v2 = acc[i][n][2] + b0, v3 = acc[i][n][3] + b1;
                    if (addend) {
                        float2 a0 = *(const float2*)(addend + (size_t)r0*ldad + gn);
                        float2 a1 = *(const float2*)(addend + (size_t)r1*ldad + gn);
                        v0 += a0.x; v1 += a0.y; v2 += a1.x; v3 += a1.y;
                    }
                    *(float2*)(C + (size_t)r0*ldc + gn) = make_float2(v0, v1);
                    *(float2*)(C + (size_t)r1*ldc + gn) = make_float2(v2, v3);
                }
            }
        }
    }
}

__global__ void casc_attn_kernel() {
    __shared__ float ks[KK][DH+1];
    __shared__ float vs[KK][DH+1];
    int bh = blockIdx.x;
    int b = bh / NHH, nh = bh % NHH;
    int t = threadIdx.x;
    const float* base = g_qkv + ((size_t)(b*KK + t)) * (3*HH);
#pragma unroll
    for (int dd = 0; dd < DH; dd++) {
        ks[t][dd] = base[HH   + nh*DH + dd];
        vs[t][dd] = base[2*HH + nh*DH + dd];
    }
    __syncthreads();
    float q[DH];
#pragma unroll
    for (int dd = 0; dd < DH; dd++) q[dd] = base[nh*DH + dd];

    const float scale = 0.125f;
    float sc[KK];
    float mx = -1e30f;
    for (int j = 0; j <= t; j++) {
        float s = 0.f;
#pragma unroll
        for (int dd = 0; dd < DH; dd++) s += q[dd] * ks[j][dd];
        s *= scale;
        sc[j] = s;
        mx = fmaxf(mx, s);
    }
    float sum = 0.f;
    for (int j = 0; j <= t; j++) {
        float e = expf(sc[j] - mx);
        sc[j] = e;
        sum += e;
    }
    float inv = 1.0f / sum;
    __half* o = h_attn + ((size_t)(b*KK + t)) * HH + nh*DH;
#pragma unroll 4
    for (int dd = 0; dd < DH; dd++) {
        float acc = 0.f;
        for (int j = 0; j <= t; j++) acc += sc[j] * vs[j][dd];
        o[dd] = __float2half(acc * inv);
    }
}

__global__ void dec_attn_kernel() {
    __shared__ float ks[KK][DH+1];
    __shared__ float vs[KK][DH+1];
    __shared__ float qs[8][DH];
    __shared__ float probs[8][KK];
    int nh = blockIdx.x, b = blockIdx.y, z = blockIdx.z;
    int tid = threadIdx.x;
    for (int i = tid; i < KK*DH; i += 256) {
        int c = i / DH, dd = i % DH;
        const float* kvrow = g_kv + ((size_t)(b*KK + c)) * (2*HH);
        ks[c][dd] = kvrow[nh*DH + dd];
        vs[c][dd] = kvrow[HH + nh*DH + dd];
    }
    __syncthreads();
    int w = tid >> 5, lane = tid & 31;
    const float scale = 0.125f;
    const int s0b = z * (SS/8), s1b = s0b + (SS/8);
    for (int s = s0b + w; s < s1b; s += 8) {
        int nallow = min(KK, s/32 + 2);
        const float* qrow = g_q + ((size_t)b*SS + s) * HH + nh*DH;
        qs[w][lane]      = qrow[lane];
        qs[w][lane + 32] = qrow[lane + 32];
        __syncwarp();
        float s0 = -INFINITY, s1 = -INFINITY;
        if (lane < nallow) {
            float acc = 0.f;
#pragma unroll
            for (int dd = 0; dd < DH; dd++) acc += qs[w][dd] * ks[lane][dd];
            s0 = acc * scale;
        }
        if (lane + 32 < nallow) {
            float acc = 0.f;
#pragma unroll
            for (int dd = 0; dd < DH; dd++) acc += qs[w][dd] * ks[lane + 32][dd];
            s1 = acc * scale;
        }
        float mx = fmaxf(s0, s1);
#pragma unroll
        for (int ofs = 16; ofs > 0; ofs >>= 1)
            mx = fmaxf(mx, __shfl_xor_sync(0xffffffffu, mx, ofs));
        float e0 = expf(s0 - mx);
        float e1 = expf(s1 - mx);
        float sum = e0 + e1;
#pragma unroll
        for (int ofs = 16; ofs > 0; ofs >>= 1)
            sum += __shfl_xor_sync(0xffffffffu, sum, ofs);
        float inv = 1.0f / sum;
        probs[w][lane]      = e0 * inv;
        probs[w][lane + 32] = e1 * inv;
        __syncwarp();
        __half* orow = h_dec + ((size_t)b*SS + s) * HH + nh*DH;
#pragma unroll
        for (int half2i = 0; half2i < 2; half2i++) {
            int dd = lane + half2i*32;
            float acc = 0.f;
            for (int j = 0; j < nallow; j++) acc += probs[w][j] * vs[j][dd];
            orow[dd] = __float2half(acc);
        }
        __syncwarp();
    }
}

template<typename T>
static T* symaddr(const void* sym) {
    void* p = nullptr;
    cudaGetSymbolAddress(&p, sym);
    return (T*)p;
}

#define SMEM_D (3*(128 + 256)*128)
#define SMEM_C (3*(64  + 128)*128)
#define SMEM_S (3*(64  + 64)*128)

extern "C" void kernel_launch(void* const* d_in, const int* in_sizes, int n_in,
                              void* d_out, int out_size) {
    const float* token       = (const float*)d_in[0];
    const float* chunk_repr  = (const float*)d_in[1];
    const float* cw          = (const float*)d_in[2];
    const float* casc_norm1  = (const float*)d_in[3];
    const float* casc_qkv    = (const float*)d_in[4];
    const float* casc_o      = (const float*)d_in[5];
    const float* casc_norm2  = (const float*)d_in[6];
    const float* casc_w1     = (const float*)d_in[7];
    const float* casc_w2     = (const float*)d_in[8];
    const float* casc_w3     = (const float*)d_in[9];
    const float* dec_in_w    = (const float*)d_in[10];
    const float* dec_in_b    = (const float*)d_in[11];
    const float* dec_out_w   = (const float*)d_in[12];
    const float* dec_out_b   = (const float*)d_in[13];
    const float* dec_norm_w  = (const float*)d_in[14];
    const float* dec_ffn_nw  = (const float*)d_in[15];
    const float* dec_w1      = (const float*)d_in[16];
    const float* dec_w2      = (const float*)d_in[17];
    const float* dec_w3      = (const float*)d_in[18];
    float* out = (float*)d_out;

    float* px    = symaddr<float>(g_x);
    float* pqkv  = symaddr<float>(g_qkv);
    float* pq    = symaddr<float>(g_q);
    float* pkv   = symaddr<float>(g_kv);
    float* py    = symaddr<float>(g_y);
    float* pyn   = symaddr<float>(g_yn);

    __half* ph_tok  = symaddr<__half>(h_tok);
    __half* ph_h    = symaddr<__half>(h_h);
    __half* ph_attn = symaddr<__half>(h_attn);
    __half* ph_proc = symaddr<__half>(h_proc);
    __half* ph_ff   = symaddr<__half>(h_ff);
    __half* ph_dec  = symaddr<__half>(h_dec);
    __half* ph_yn   = symaddr<__half>(h_yn);
    __half* ph_u    = symaddr<__half>(h_u);

    __half* pw_qkv  = symaddr<__half>(wh_qkv);
    __half* pw_o    = symaddr<__half>(wh_o);
    __half* pw_w13  = symaddr<__half>(wh_w13);
    __half* pw_w2   = symaddr<__half>(wh_w2);
    __half* pw_din  = symaddr<__half>(wh_din);
    __half* pw_dout = symaddr<__half>(wh_dout);
    __half* pw_dw13 = symaddr<__half>(wh_dw13);
    __half* pw_dw2  = symaddr<__half>(wh_dw2);

    cudaFuncSetAttribute((const void*)hgemm<128,256,2,8,0>,
                         cudaFuncAttributeMaxDynamicSharedMemorySize, SMEM_D);
    cudaFuncSetAttribute((const void*)hgemm<128,256,2,8,1>,
                         cudaFuncAttributeMaxDynamicSharedMemorySize, SMEM_D);
    cudaFuncSetAttribute((const void*)hgemm<64,128,2,8,0>,
                         cudaFuncAttributeMaxDynamicSharedMemorySize, SMEM_C);
    cudaFuncSetAttribute((const void*)hgemm<64,128,2,8,1>,
                         cudaFuncAttributeMaxDynamicSharedMemorySize, SMEM_C);
    cudaFuncSetAttribute((const void*)hgemm<64,64,4,4,0>,
                         cudaFuncAttributeMaxDynamicSharedMemorySize, SMEM_S);

    auto gemmD = [&](cudaStream_t st, const __half* A, int lda, const __half* W, int ldw,
                     const float* bias, const float* addend, int ldad,
                     void* C, int ldc, int M, int N, int Kd, bool glu) {
        dim3 grid((N + 255)/256, M/128);
        if (glu)
            hgemm<128,256,2,8,1><<<grid, NTH, SMEM_D, st>>>(A, lda, W, ldw, bias, addend, ldad,
                                                            C, ldc, M, N, Kd);
        else
            hgemm<128,256,2,8,0><<<grid, NTH, SMEM_D, st>>>(A, lda, W, ldw, bias, addend, ldad,
                                                            C, ldc, M, N, Kd);
    };
    auto gemmC = [&](cudaStream_t st, const __half* A, int lda, const __half* W, int ldw,
                     const float* bias, const float* addend, int ldad,
                     void* C, int ldc, int M, int N, int Kd, bool glu) {
        dim3 grid((N + 127)/128, M/64);
        if (glu)
            hgemm<64,128,2,8,1><<<grid, NTH, SMEM_C, st>>>(A, lda, W, ldw, bias, addend, ldad,
                                                           C, ldc, M, N, Kd);
        else
            hgemm<64,128,2,8,0><<<grid, NTH, SMEM_C, st>>>(A, lda, W, ldw, bias, addend, ldad,
                                                           C, ldc, M, N, Kd);
    };
    // small-tile variant for cascade N=1024 GEMMs (more CTAs on serial path)
    auto gemmS = [&](cudaStream_t st, const __half* A, int lda, const __half* W, int ldw,
                     const float* bias, const float* addend, int ldad,
                     void* C, int ldc, int M, int N, int Kd) {
        dim3 grid((N + 63)/64, M/64);
        hgemm<64,64,4,4,0><<<grid, NTH, SMEM_S, st>>>(A, lda, W, ldw, bias, addend, ldad,
                                                      C, ldc, M, N, Kd);
    };

    cudaStream_t main0 = 0;
    cudaStream_t side;
    cudaStreamCreateWithFlags(&side, cudaStreamNonBlocking);
    cudaEvent_t evFork, evJoin;
    cudaEventCreateWithFlags(&evFork, cudaEventDisableTiming);
    cudaEventCreateWithFlags(&evJoin, cudaEventDisableTiming);

    // ---- fork: side = decoder prep + q projection (R11 schedule) ----
    cudaEventRecord(evFork, main0);
    cudaStreamWaitEvent(side, evFork, 0);
    halfcopy_kernel<<<2048, 256, 0, side>>>(dec_in_w,  pw_din,  3*HH*HH/2);
    halfcopy_kernel<<<2048, 256, 0, side>>>(dec_out_w, pw_dout, HH*HH/2);
    w13i_kernel<<<FI2, 256, 0, side>>>(dec_w1, dec_w3, pw_dw13);
    w2half_kernel<<<HH, 256, 0, side>>>(dec_w2, pw_dw2);
    halfcopy_kernel<<<4096, 256, 0, side>>>(token, ph_tok, BB*SS*HH/2);
    gemmD(side, ph_tok, HH, pw_din, HH,
          dec_in_b, nullptr, 0, pq, HH, BB*SS, HH, HH, false);
    cudaEventRecord(evJoin, side);

    // ---- main: cascade weight prep + cascade ----
    halfcopy_kernel<<<2048, 256>>>(casc_qkv, pw_qkv, LL*3*HH*HH/2);
    halfcopy_kernel<<<2048, 256>>>(casc_o,   pw_o,   LL*HH*HH/2);
    for (int l = 0; l < LL; l++) {
        w13i_kernel<<<FI2, 256>>>(casc_w1 + (size_t)l*FFD*HH,
                                  casc_w3 + (size_t)l*FFD*HH,
                                  pw_w13 + (size_t)l*FI2*HH);
        w2half_kernel<<<HH, 256>>>(casc_w2 + (size_t)l*HH*FFD,
                                   pw_w2 + (size_t)l*HH*FFH);
    }
    rank_kernel<<<BB, KK>>>(cw);
    scatter_kernel<<<BB*KK, 256>>>(chunk_repr);

    const int MC = BB*KK;
    for (int l = 0; l < LL; l++) {
        rms_kernel<__half><<<MC, 256>>>(px, casc_norm1 + l*HH, ph_h);
        gemmC(main0, ph_h, HH, pw_qkv + (size_t)l*3*HH*HH, HH,
              nullptr, nullptr, 0, pqkv, 3*HH, MC, 3*HH, HH, false);
        casc_attn_kernel<<<BB*NHH, KK>>>();
        gemmS(main0, ph_attn, HH, pw_o + (size_t)l*HH*HH, HH,
              nullptr, px, HH, px, HH, MC, HH, HH);
        rms_kernel<__half><<<MC, 256>>>(px, casc_norm2 + l*HH, ph_h);
        gemmC(main0, ph_h, HH, pw_w13 + (size_t)l*FI2*HH, HH,
              nullptr, nullptr, 0, ph_ff, FFH, MC, FI2, HH, true);
        gemmS(main0, ph_ff, FFH, pw_w2 + (size_t)l*HH*FFH, FFH,
              nullptr, px, HH, px, HH, MC, HH, FFH);
    }
    gather_kernel<<<BB*KK, 256>>>();

    // ---- join BEFORE kv gemm (it reads pw_din produced on side) ----
    cudaStreamWaitEvent(main0, evJoin, 0);
    gemmC(main0, ph_proc, HH, pw_din + (size_t)HH*HH, HH,
          dec_in_b + HH, nullptr, 0, pkv, 2*HH, MC, 2*HH, HH, false);
    dec_attn_kernel<<<dim3(NHH, BB, 8), 256>>>();

    const int MT = BB*SS;
    gemmD(main0, ph_dec, HH, pw_dout, HH,
          dec_out_b, token, HH, pyn, HH, MT, HH, HH, false);
    rms2_kernel<<<MT, 256>>>(pyn, dec_norm_w, dec_ffn_nw, py, ph_yn);
    gemmD(main0, ph_yn, HH, pw_dw13, HH,
          nullptr, nullptr, 0, ph_u, FFH, MT, FI2, HH, true);
    gemmD(main0, ph_u, FFH, pw_dw2, FFH,
          nullptr, py, HH, out, HH, MT, HH, FFH, false);
}